// round 6
// baseline (speedup 1.0000x reference)
#include <cuda_runtime.h>
#include <math.h>
#include <stdint.h>

// ---------------- problem constants ----------------
#define NBATCH 4096
#define NTOK   64
#define MTOT   (NBATCH * NTOK)
#define DOBS   128

// ---------------- packed tf32 weight buffers ----------------
#define P_E1  0                      // 128x128 -> 16384 floats
#define P_E2  16384                  // 128x64  ->  8192
#define P_QK  24576                  // 64x192  -> 12288
#define P_I1  36864                  // 192x256 -> 49152 (combined int_w1 / out_w@int_w1)
#define P_I2  86016                  // 256x128 -> 32768
#define P_TOT 118784
__device__ float g_pack[P_TOT];
__device__ float g_Wc[64 * 256];
__device__ float g_bc[256];
__device__ float g_Wcomb[192 * 256];
__device__ float g_ctx[(size_t)MTOT * 64];
__device__ float g_msgs_s[(size_t)MTOT * 64];

// ---------------- helpers ----------------
__device__ __forceinline__ uint32_t f2tf(float x) {
    uint32_t u;
    asm("cvt.rna.tf32.f32 %0, %1;" : "=r"(u) : "f"(x));
    return u;
}
__device__ __forceinline__ uint32_t smem_u32(const void* p) {
    uint32_t a;
    asm("{ .reg .u64 t; cvta.to.shared.u64 t, %1; cvt.u32.u64 %0, t; }" : "=r"(a) : "l"(p));
    return a;
}
__device__ __forceinline__ void cp16(uint32_t dst, const float* src) {
    asm volatile("cp.async.ca.shared.global [%0], [%1], 16;" :: "r"(dst), "l"(src));
}
#define CP_COMMIT() asm volatile("cp.async.commit_group;" ::: "memory")
#define CP_WAIT(n)  asm volatile("cp.async.wait_group %0;" :: "n"(n) : "memory")

#define MMA_TF32(acc, a, bx, by)                                                     \
    asm volatile("mma.sync.aligned.m16n8k8.row.col.f32.tf32.tf32.f32 "               \
                 "{%0,%1,%2,%3}, {%4,%5,%6,%7}, {%8,%9}, {%0,%1,%2,%3};"             \
                 : "+f"((acc)[0]), "+f"((acc)[1]), "+f"((acc)[2]), "+f"((acc)[3])    \
                 : "r"((a)[0]), "r"((a)[1]), "r"((a)[2]), "r"((a)[3]),               \
                   "r"(bx), "r"(by))

// ---------------- weight prep (tiny, per launch) ----------------
__global__ void pack_w(const float* __restrict__ W, int K, int N, float* __restrict__ dst)
{
    int gid = blockIdx.x * blockDim.x + threadIdx.x;
    int total = K * N / 2;
    if (gid >= total) return;
    int lane = gid & 31;
    int tile = gid >> 5;
    int nt = N >> 3;
    int j = tile % nt, kk = tile / nt;
    int t = lane & 3, g = lane >> 2;
    int k = kk * 8 + t, n = j * 8 + g;
    float2 v;
    v.x = __uint_as_float(f2tf(W[(size_t)k * N + n]));
    v.y = __uint_as_float(f2tf(W[(size_t)(k + 4) * N + n]));
    ((float2*)dst)[gid] = v;
}

__global__ void prep_wc(const float* __restrict__ out_w, const float* __restrict__ out_b,
                        const float* __restrict__ int_w1, const float* __restrict__ int_b1)
{
    int i = blockIdx.x * blockDim.x + threadIdx.x;
    if (i < 64 * 256) {
        int c = i >> 8, n = i & 255;
        float s = 0.f;
        for (int m = 0; m < 64; m++) s = fmaf(out_w[c * 64 + m], int_w1[(128 + m) * 256 + n], s);
        g_Wc[i] = s;
    }
    if (i < 256) {
        float s = int_b1[i];
        for (int m = 0; m < 64; m++) s = fmaf(out_b[m], int_w1[(128 + m) * 256 + i], s);
        g_bc[i] = s;
    }
}

__global__ void combine_w(const float* __restrict__ int_w1)
{
    int i = blockIdx.x * blockDim.x + threadIdx.x;
    if (i >= 192 * 256) return;
    int row = i >> 8;
    g_Wcomb[i] = (row < 128) ? int_w1[i] : g_Wc[i - 128 * 256];
}

// ---------------- smem-A, streamed-B mma stage ----------------
// Y[64 x N] = relu?(sX[64 x K] @ W + bias). B streamed cp.async double-buffered.
// Y may be smem (LDY padded) or gmem (LDY = N). Caller syncs after if Y is smem.
template<int K, int N, int LDX, int LDY, bool RELU>
__device__ __forceinline__ void stage_s(int tid, const float* sX,
                                        const float* __restrict__ packB,
                                        const float* sBias, float* Y,
                                        float* sB, uint32_t sB_addr)
{
    constexpr int NCH = K / 32, NT = N / 32, SB = 32 * N;
    const int lane = tid & 31, w = tid >> 5;
    const int wr = w >> 2, wc = w & 3;
    const int t = lane & 3, g = lane >> 2;
    const int r0 = wr * 32;

    float acc[2][NT][4];
#pragma unroll
    for (int mt = 0; mt < 2; mt++)
#pragma unroll
        for (int j = 0; j < NT; j++)
            acc[mt][j][0] = acc[mt][j][1] = acc[mt][j][2] = acc[mt][j][3] = 0.f;

    auto issueB = [&](int c, int buf) {
        const float* bs = packB + (size_t)c * SB;
        for (int e = tid; e < SB / 4; e += 256)
            cp16(sB_addr + (uint32_t)(buf * SB + e * 4) * 4, bs + e * 4);
    };
    issueB(0, 0);
    CP_COMMIT();

#pragma unroll 1
    for (int c = 0; c < NCH; c++) {
        if (c + 1 < NCH) { issueB(c + 1, (c + 1) & 1); CP_COMMIT(); CP_WAIT(1); }
        else             { CP_WAIT(0); }
        __syncthreads();
        const float2* sBf = (const float2*)(sB + (c & 1) * SB);
        const int kb0 = c * 32;
#pragma unroll
        for (int kl = 0; kl < 4; kl++) {
            uint32_t a[2][4];
#pragma unroll
            for (int mt = 0; mt < 2; mt++) {
                const int rb = r0 + mt * 16 + g;
                a[mt][0] = f2tf(sX[rb * LDX + kb0 + kl * 8 + t]);
                a[mt][1] = f2tf(sX[(rb + 8) * LDX + kb0 + kl * 8 + t]);
                a[mt][2] = f2tf(sX[rb * LDX + kb0 + kl * 8 + t + 4]);
                a[mt][3] = f2tf(sX[(rb + 8) * LDX + kb0 + kl * 8 + t + 4]);
            }
#pragma unroll
            for (int j = 0; j < NT; j++) {
                float2 bv = sBf[(size_t)(kl * (N / 8) + wc * NT + j) * 32 + lane];
                const uint32_t bx = __float_as_uint(bv.x), by = __float_as_uint(bv.y);
#pragma unroll
                for (int mt = 0; mt < 2; mt++)
                    MMA_TF32(acc[mt][j], a[mt], bx, by);
            }
        }
        __syncthreads();
    }
#pragma unroll
    for (int mt = 0; mt < 2; mt++)
#pragma unroll
        for (int j = 0; j < NT; j++) {
            const int n0 = wc * (N / 4) + j * 8 + 2 * t;
            const float b0 = sBias[n0], b1 = sBias[n0 + 1];
            float v0 = acc[mt][j][0] + b0, v1 = acc[mt][j][1] + b1;
            float v2 = acc[mt][j][2] + b0, v3 = acc[mt][j][3] + b1;
            if (RELU) { v0 = fmaxf(v0, 0.f); v1 = fmaxf(v1, 0.f);
                        v2 = fmaxf(v2, 0.f); v3 = fmaxf(v3, 0.f); }
            const size_t rA = (size_t)(r0 + mt * 16 + g);
            *(float2*)(Y + rA * LDY + n0)       = make_float2(v0, v1);
            *(float2*)(Y + (rA + 8) * LDY + n0) = make_float2(v2, v3);
        }
}

// ---------------- front kernel: obs -> msgs, ctx (per batch) ----------------
#define LD_A  132
#define LD_M  68
#define LD_Q  196
#define LD_C  68
#define F_OBS 384
#define F_H   8832
#define F_MSG 17280
#define F_QKV 21632
#define F_B   34176
#define F_TOT 46464   // floats -> 185856 bytes

__global__ void __launch_bounds__(256)
front_kernel(const float* __restrict__ obs,
             const float* __restrict__ enc_b1, const float* __restrict__ enc_b2,
             const float* __restrict__ inp_b,  const float* __restrict__ pack,
             float* __restrict__ outM, float* __restrict__ outC)
{
    extern __shared__ float sm[];
    const int tid = threadIdx.x, b = blockIdx.x;
    const uint32_t sbase = smem_u32(sm);

    for (int i = tid; i < 128; i += 256) sm[i] = enc_b1[i];
    if (tid < 64) sm[128 + tid] = enc_b2[tid];
    for (int i = tid; i < 192; i += 256) sm[192 + i] = inp_b[i];

    // obs tile via cp.async (own group; drained by enc1's first wait)
    {
        const float* gs = obs + (size_t)b * NTOK * DOBS;
        for (int e = tid; e < NTOK * DOBS / 4; e += 256) {
            int r = e >> 5, c4 = e & 31;
            cp16(sbase + (uint32_t)(F_OBS + r * LD_A + c4 * 4) * 4, gs + r * DOBS + c4 * 4);
        }
        CP_COMMIT();
    }

    // enc1: h = relu(obs @ W1 + b1)
    stage_s<128, 128, LD_A, LD_A, true>(tid, sm + F_OBS, pack + P_E1, sm + 0,
                                        sm + F_H, sm + F_B, sbase + F_B * 4);
    __syncthreads();
    // enc2: msgs = h @ W2 + b2
    stage_s<128, 64, LD_A, LD_M, false>(tid, sm + F_H, pack + P_E2, sm + 128,
                                        sm + F_MSG, sm + F_B, sbase + F_B * 4);
    __syncthreads();
    // msgs -> gmem
    {
        float4* gm = (float4*)(outM + (size_t)b * NTOK * 64);
        for (int e = tid; e < NTOK * 64 / 4; e += 256) {
            int r = e >> 4, c4 = e & 15;
            gm[e] = *(const float4*)(sm + F_MSG + r * LD_M + c4 * 4);
        }
    }
    // qkv = msgs @ in_proj + b
    stage_s<64, 192, LD_M, LD_Q, false>(tid, sm + F_MSG, pack + P_QK, sm + 192,
                                        sm + F_QKV, sm + F_B, sbase + F_B * 4);
    __syncthreads();

    // attention (scalar, validated): thread = (head, query)
    {
        const int h = tid >> 6, q = tid & 63;
        const float* sQ = sm + F_QKV;
        float qv[16];
#pragma unroll
        for (int d = 0; d < 16; d++) qv[d] = sQ[q * LD_Q + h * 16 + d];
        float m = -1e30f;
#pragma unroll 4
        for (int k = 0; k < 64; k++) {
            const float* kp = sQ + k * LD_Q + 64 + h * 16;
            float s = 0.f;
#pragma unroll
            for (int d = 0; d < 16; d++) s = fmaf(qv[d], kp[d], s);
            m = fmaxf(m, s * 0.25f);
        }
        float ssum = 0.f, ctx[16];
#pragma unroll
        for (int d = 0; d < 16; d++) ctx[d] = 0.f;
#pragma unroll 2
        for (int k = 0; k < 64; k++) {
            const float* kp = sQ + k * LD_Q + 64 + h * 16;
            float s = 0.f;
#pragma unroll
            for (int d = 0; d < 16; d++) s = fmaf(qv[d], kp[d], s);
            float p = __expf(fmaf(s, 0.25f, -m));
            ssum += p;
            const float* vp = sQ + k * LD_Q + 128 + h * 16;
#pragma unroll
            for (int d = 0; d < 16; d++) ctx[d] = fmaf(p, vp[d], ctx[d]);
        }
        float inv = 1.f / ssum;
        float* sC = sm + F_OBS;   // obs dead after enc1
#pragma unroll
        for (int d = 0; d < 16; d++) sC[q * LD_C + h * 16 + d] = ctx[d] * inv;
    }
    __syncthreads();
    // ctx -> gmem
    {
        float4* go = (float4*)(outC + (size_t)b * NTOK * 64);
        for (int e = tid; e < NTOK * 64 / 4; e += 256) {
            int r = e >> 4, c4 = e & 15;
            go[e] = *(const float4*)(sm + F_OBS + r * LD_C + c4 * 4);
        }
    }
}

// ---------------- back kernel: [obs|ctx] -> int1+LN+relu -> int2 -> out ----------------
#define B_R   896
#define B_A   1408
#define B_Z   6016
#define B_B   22656
#define B_TOT 39040   // floats -> 156160 bytes
#define LD_Z  260

__global__ void __launch_bounds__(256)
back_kernel(const float* __restrict__ obs, const float* __restrict__ ctx,
            const float* __restrict__ bc, const float* __restrict__ lng,
            const float* __restrict__ lnb, const float* __restrict__ int_b2,
            const float* __restrict__ packI1, const float* __restrict__ packI2,
            float* __restrict__ outE)
{
    extern __shared__ float sm[];
    const int tid = threadIdx.x, b = blockIdx.x;
    const int m0 = b * 64;
    const uint32_t sbase = smem_u32(sm);

    for (int i = tid; i < 256; i += 256) { sm[i] = bc[i]; sm[256 + i] = lng[i]; sm[512 + i] = lnb[i]; }
    if (tid < 128) sm[768 + tid] = int_b2[tid];

    const int lane = tid & 31, w = tid >> 5;
    const int wr = w >> 2, wc = w & 3;
    const int t = lane & 3, g = lane >> 2;
    const int r0 = wr * 32;

    // ---- int1: z = LN(relu([obs|ctx] @ Wcomb + bc)), A and B streamed ----
    {
        constexpr int N = 256, NCH = 6, NT = 8, SB = 32 * N, SA = 64 * 36;
        float acc[2][NT][4];
#pragma unroll
        for (int mt = 0; mt < 2; mt++)
#pragma unroll
            for (int j = 0; j < NT; j++)
                acc[mt][j][0] = acc[mt][j][1] = acc[mt][j][2] = acc[mt][j][3] = 0.f;

        auto issue = [&](int c, int buf) {
            const int gc0 = c * 32;
#pragma unroll
            for (int e = tid; e < 512; e += 256) {
                int row = e >> 3, cq = e & 7;
                int gcol = gc0 + cq * 4;
                const float* src = (gcol >= 128)
                    ? ctx + (size_t)(m0 + row) * 64 + (gcol - 128)
                    : obs + (size_t)(m0 + row) * 128 + gcol;
                cp16(sbase + (uint32_t)(B_A + buf * SA + row * 36 + cq * 4) * 4, src);
            }
            const float* bs = packI1 + (size_t)c * SB;
            for (int e = tid; e < SB / 4; e += 256)
                cp16(sbase + (uint32_t)(B_B + buf * SB + e * 4) * 4, bs + e * 4);
        };
        issue(0, 0);
        CP_COMMIT();

#pragma unroll 1
        for (int c = 0; c < NCH; c++) {
            if (c + 1 < NCH) { issue(c + 1, (c + 1) & 1); CP_COMMIT(); CP_WAIT(1); }
            else             { CP_WAIT(0); }
            __syncthreads();
            const float* sA = sm + B_A + (c & 1) * SA;
            const float2* sBf = (const float2*)(sm + B_B + (c & 1) * SB);
#pragma unroll
            for (int kl = 0; kl < 4; kl++) {
                uint32_t a[2][4];
#pragma unroll
                for (int mt = 0; mt < 2; mt++) {
                    const int rb = r0 + mt * 16 + g;
                    a[mt][0] = f2tf(sA[rb * 36 + kl * 8 + t]);
                    a[mt][1] = f2tf(sA[(rb + 8) * 36 + kl * 8 + t]);
                    a[mt][2] = f2tf(sA[rb * 36 + kl * 8 + t + 4]);
                    a[mt][3] = f2tf(sA[(rb + 8) * 36 + kl * 8 + t + 4]);
                }
#pragma unroll
                for (int j = 0; j < NT; j++) {
                    float2 bv = sBf[(size_t)(kl * (N / 8) + wc * NT + j) * 32 + lane];
                    const uint32_t bx = __float_as_uint(bv.x), by = __float_as_uint(bv.y);
#pragma unroll
                    for (int mt = 0; mt < 2; mt++)
                        MMA_TF32(acc[mt][j], a[mt], bx, by);
                }
            }
            __syncthreads();
        }

        // epilogue: bias + LayerNorm + relu -> z smem
#pragma unroll
        for (int mt = 0; mt < 2; mt++)
#pragma unroll
            for (int j = 0; j < NT; j++) {
                const int n0 = wc * (N / 4) + j * 8 + 2 * t;
                acc[mt][j][0] += sm[n0]; acc[mt][j][1] += sm[n0 + 1];
                acc[mt][j][2] += sm[n0]; acc[mt][j][3] += sm[n0 + 1];
            }
        float ps[2][2] = {{0,0},{0,0}}, pq[2][2] = {{0,0},{0,0}};
#pragma unroll
        for (int mt = 0; mt < 2; mt++)
#pragma unroll
            for (int j = 0; j < NT; j++) {
                ps[mt][0] += acc[mt][j][0] + acc[mt][j][1];
                pq[mt][0] += acc[mt][j][0] * acc[mt][j][0] + acc[mt][j][1] * acc[mt][j][1];
                ps[mt][1] += acc[mt][j][2] + acc[mt][j][3];
                pq[mt][1] += acc[mt][j][2] * acc[mt][j][2] + acc[mt][j][3] * acc[mt][j][3];
            }
#pragma unroll
        for (int mt = 0; mt < 2; mt++)
#pragma unroll
            for (int h = 0; h < 2; h++) {
                ps[mt][h] += __shfl_xor_sync(0xffffffffu, ps[mt][h], 1);
                ps[mt][h] += __shfl_xor_sync(0xffffffffu, ps[mt][h], 2);
                pq[mt][h] += __shfl_xor_sync(0xffffffffu, pq[mt][h], 1);
                pq[mt][h] += __shfl_xor_sync(0xffffffffu, pq[mt][h], 2);
            }
        if (t == 0) {
#pragma unroll
            for (int mt = 0; mt < 2; mt++)
#pragma unroll
                for (int h = 0; h < 2; h++) {
                    const int rl = r0 + mt * 16 + g + 8 * h;
                    sm[B_R + rl * 4 + wc]       = ps[mt][h];
                    sm[B_R + 256 + rl * 4 + wc] = pq[mt][h];
                }
        }
        __syncthreads();
        float mu[2][2], rs[2][2];
#pragma unroll
        for (int mt = 0; mt < 2; mt++)
#pragma unroll
            for (int h = 0; h < 2; h++) {
                const int rl = r0 + mt * 16 + g + 8 * h;
                float s_ = sm[B_R + rl * 4] + sm[B_R + rl * 4 + 1]
                         + sm[B_R + rl * 4 + 2] + sm[B_R + rl * 4 + 3];
                float q_ = sm[B_R + 256 + rl * 4] + sm[B_R + 256 + rl * 4 + 1]
                         + sm[B_R + 256 + rl * 4 + 2] + sm[B_R + 256 + rl * 4 + 3];
                float m_ = s_ * (1.f / N);
                float v_ = q_ * (1.f / N) - m_ * m_;
                mu[mt][h] = m_;
                rs[mt][h] = rsqrtf(v_ + 1e-5f);
            }
#pragma unroll
        for (int mt = 0; mt < 2; mt++)
#pragma unroll
            for (int j = 0; j < NT; j++) {
                const int n0 = wc * (N / 4) + j * 8 + 2 * t;
                const float g0 = sm[256 + n0], g1 = sm[256 + n0 + 1];
                const float b0 = sm[512 + n0], b1 = sm[512 + n0 + 1];
                float v0 = fmaxf((acc[mt][j][0] - mu[mt][0]) * rs[mt][0] * g0 + b0, 0.f);
                float v1 = fmaxf((acc[mt][j][1] - mu[mt][0]) * rs[mt][0] * g1 + b1, 0.f);
                float v2 = fmaxf((acc[mt][j][2] - mu[mt][1]) * rs[mt][1] * g0 + b0, 0.f);
                float v3 = fmaxf((acc[mt][j][3] - mu[mt][1]) * rs[mt][1] * g1 + b1, 0.f);
                const int rA = r0 + mt * 16 + g;
                *(float2*)(sm + B_Z + (size_t)rA * LD_Z + n0)       = make_float2(v0, v1);
                *(float2*)(sm + B_Z + (size_t)(rA + 8) * LD_Z + n0) = make_float2(v2, v3);
            }
    }
    __syncthreads();

    // ---- int2: enriched = z @ W2' + b2' -> gmem ----
    stage_s<256, 128, LD_Z, 128, false>(tid, sm + B_Z, packI2, sm + 768,
                                        outE + (size_t)m0 * 128, sm + B_B, sbase + B_B * 4);
}

// ---------------- launch ----------------
extern "C" void kernel_launch(void* const* d_in, const int* in_sizes, int n_in,
                              void* d_out, int out_size)
{
    const float* obs    = (const float*)d_in[0];
    const float* enc_w1 = (const float*)d_in[1];
    const float* enc_b1 = (const float*)d_in[2];
    const float* enc_w2 = (const float*)d_in[3];
    const float* enc_b2 = (const float*)d_in[4];
    const float* inp_w  = (const float*)d_in[5];
    const float* inp_b  = (const float*)d_in[6];
    const float* out_w  = (const float*)d_in[7];
    const float* out_b  = (const float*)d_in[8];
    const float* int_w1 = (const float*)d_in[9];
    const float* int_b1 = (const float*)d_in[10];
    const float* ln_g   = (const float*)d_in[11];
    const float* ln_b   = (const float*)d_in[12];
    const float* int_w2 = (const float*)d_in[13];
    const float* int_b2 = (const float*)d_in[14];

    float* outE = (float*)d_out;
    const size_t esz = (size_t)MTOT * DOBS;
    float* outM = ((size_t)out_size > esz) ? outE + esz : nullptr;

    float *p_pack, *p_bc, *p_comb, *p_ctx, *p_msgs;
    cudaGetSymbolAddress((void**)&p_pack, g_pack);
    cudaGetSymbolAddress((void**)&p_bc,   g_bc);
    cudaGetSymbolAddress((void**)&p_comb, g_Wcomb);
    cudaGetSymbolAddress((void**)&p_ctx,  g_ctx);
    cudaGetSymbolAddress((void**)&p_msgs, g_msgs_s);
    float* msgs = outM ? outM : p_msgs;

    const int sm_front = F_TOT * 4;
    const int sm_back  = B_TOT * 4;
    cudaFuncSetAttribute(front_kernel, cudaFuncAttributeMaxDynamicSharedMemorySize, sm_front);
    cudaFuncSetAttribute(back_kernel,  cudaFuncAttributeMaxDynamicSharedMemorySize, sm_back);

    // weight prep
    prep_wc<<<64, 256>>>(out_w, out_b, int_w1, int_b1);
    combine_w<<<192, 256>>>(int_w1);
    pack_w<<<32, 256>>>(enc_w1, 128, 128, p_pack + P_E1);
    pack_w<<<16, 256>>>(enc_w2, 128, 64,  p_pack + P_E2);
    pack_w<<<24, 256>>>(inp_w,  64,  192, p_pack + P_QK);
    pack_w<<<96, 256>>>(p_comb, 192, 256, p_pack + P_I1);
    pack_w<<<64, 256>>>(int_w2, 256, 128, p_pack + P_I2);

    front_kernel<<<NBATCH, 256, sm_front>>>(obs, enc_b1, enc_b2, inp_b, p_pack, msgs, p_ctx);
    back_kernel<<<NBATCH, 256, sm_back>>>(obs, p_ctx, p_bc, ln_g, ln_b, int_b2,
                                          p_pack + P_I1, p_pack + P_I2, outE);
}

// round 7
// speedup vs baseline: 1.0613x; 1.0613x over previous
#include <cuda_runtime.h>
#include <math.h>
#include <stdint.h>

// ---------------- problem constants ----------------
#define NBATCH 4096
#define NTOK   64
#define MTOT   (NBATCH * NTOK)
#define DOBS   128

// ---------------- packed tf32 weight buffers ----------------
#define P_E1  0                      // 128x128 -> 16384 floats
#define P_E2  16384                  // 128x64  ->  8192
#define P_QK  24576                  // 64x192  -> 12288
#define P_I1  36864                  // 192x256 -> 49152 (combined int_w1 / out_w@int_w1)
#define P_I2  86016                  // 256x128 -> 32768
#define P_TOT 118784
__device__ float g_pack[P_TOT];
__device__ float g_bc[256];
__device__ float g_h[(size_t)MTOT * 128];
__device__ float g_qkv[(size_t)MTOT * 192];
__device__ float g_ctx[(size_t)MTOT * 64];
__device__ float g_z[(size_t)MTOT * 256];
__device__ float g_msgs_s[(size_t)MTOT * 64];

// ---------------- helpers ----------------
__device__ __forceinline__ uint32_t f2tf(float x) {
    uint32_t u;
    asm("cvt.rna.tf32.f32 %0, %1;" : "=r"(u) : "f"(x));
    return u;
}
__device__ __forceinline__ float f2tf_f(float x) { return __uint_as_float(f2tf(x)); }
__device__ __forceinline__ uint32_t smem_u32(const void* p) {
    uint32_t a;
    asm("{ .reg .u64 t; cvta.to.shared.u64 t, %1; cvt.u32.u64 %0, t; }" : "=r"(a) : "l"(p));
    return a;
}
__device__ __forceinline__ void cp16(uint32_t dst, const float* src) {
    asm volatile("cp.async.ca.shared.global [%0], [%1], 16;" :: "r"(dst), "l"(src));
}
#define CP_COMMIT() asm volatile("cp.async.commit_group;" ::: "memory")
#define CP_WAIT(n)  asm volatile("cp.async.wait_group %0;" :: "n"(n) : "memory")

#define MMA_TF32(acc, a, bx, by)                                                     \
    asm volatile("mma.sync.aligned.m16n8k8.row.col.f32.tf32.tf32.f32 "               \
                 "{%0,%1,%2,%3}, {%4,%5,%6,%7}, {%8,%9}, {%0,%1,%2,%3};"             \
                 : "+f"((acc)[0]), "+f"((acc)[1]), "+f"((acc)[2]), "+f"((acc)[3])    \
                 : "r"((a)[0]), "r"((a)[1]), "r"((a)[2]), "r"((a)[3]),               \
                   "r"(bx), "r"(by))

// ---------------- single prep kernel: fold + pack everything ----------------
// pair regions: E1 [0,8192) E2 [8192,12288) QK [12288,18432) I2 [18432,34816)
//               I1 [34816,59392) bc [59392,59648)
__device__ __forceinline__ float wcomb_elem(int k, int n,
                                            const float* __restrict__ out_w,
                                            const float* __restrict__ int_w1)
{
    if (k < 128) return int_w1[(size_t)k * 256 + n];
    const int c = k - 128;
    float s = 0.f;
#pragma unroll 4
    for (int m = 0; m < 64; m++)
        s = fmaf(out_w[c * 64 + m], int_w1[(size_t)(128 + m) * 256 + n], s);
    return s;
}

__global__ void pack_all(const float* __restrict__ enc_w1, const float* __restrict__ enc_w2,
                         const float* __restrict__ inp_w,  const float* __restrict__ out_w,
                         const float* __restrict__ out_b,  const float* __restrict__ int_w1,
                         const float* __restrict__ int_b1, const float* __restrict__ int_w2)
{
    const int gid = blockIdx.x * blockDim.x + threadIdx.x;
    int p;
    const float* W = nullptr;
    float* dst = nullptr;
    int K = 0, N = 0;
    bool i1 = false;
    if (gid < 8192)        { p = gid;          W = enc_w1; dst = g_pack + P_E1; K = 128; N = 128; }
    else if (gid < 12288)  { p = gid - 8192;   W = enc_w2; dst = g_pack + P_E2; K = 128; N = 64;  }
    else if (gid < 18432)  { p = gid - 12288;  W = inp_w;  dst = g_pack + P_QK; K = 64;  N = 192; }
    else if (gid < 34816)  { p = gid - 18432;  W = int_w2; dst = g_pack + P_I2; K = 256; N = 128; }
    else if (gid < 59392)  { p = gid - 34816;  dst = g_pack + P_I1; K = 192; N = 256; i1 = true; }
    else if (gid < 59648) {
        const int n = gid - 59392;
        float s = int_b1[n];
        for (int m = 0; m < 64; m++) s = fmaf(out_b[m], int_w1[(size_t)(128 + m) * 256 + n], s);
        g_bc[n] = s;
        return;
    } else return;

    const int lane = p & 31;
    const int tile = p >> 5;
    const int nt = N >> 3;
    const int j = tile % nt, kk = tile / nt;
    const int t = lane & 3, g = lane >> 2;
    const int k = kk * 8 + t, n = j * 8 + g;
    float vx, vy;
    if (i1) { vx = wcomb_elem(k, n, out_w, int_w1); vy = wcomb_elem(k + 4, n, out_w, int_w1); }
    else    { vx = W[(size_t)k * N + n];            vy = W[(size_t)(k + 4) * N + n]; }
    float2 v;
    v.x = f2tf_f(vx);
    v.y = f2tf_f(vy);
    ((float2*)dst)[p] = v;
}

// ---------------- chunk compute: 4 k-steps of mma from smem ----------------
template<int NT, bool CVT>
__device__ __forceinline__ void chunk_mma(const float* sA, const float2* sBf,
                                          float (&acc)[2][NT][4],
                                          int r0, int wc, int t, int g)
{
    const int lane = g * 4 + t;
#pragma unroll
    for (int kl = 0; kl < 4; kl++) {
        uint32_t a[2][4];
#pragma unroll
        for (int mt = 0; mt < 2; mt++) {
            const int rb = r0 + mt * 16 + g;
            const float x0 = sA[rb * 36 + kl * 8 + t];
            const float x1 = sA[(rb + 8) * 36 + kl * 8 + t];
            const float x2 = sA[rb * 36 + kl * 8 + t + 4];
            const float x3 = sA[(rb + 8) * 36 + kl * 8 + t + 4];
            if (CVT) {
                a[mt][0] = f2tf(x0); a[mt][1] = f2tf(x1);
                a[mt][2] = f2tf(x2); a[mt][3] = f2tf(x3);
            } else {
                a[mt][0] = __float_as_uint(x0); a[mt][1] = __float_as_uint(x1);
                a[mt][2] = __float_as_uint(x2); a[mt][3] = __float_as_uint(x3);
            }
        }
#pragma unroll
        for (int j = 0; j < NT; j++) {
            const float2 bv = sBf[(size_t)(kl * 4 * NT + wc * NT + j) * 32 + lane];
            const uint32_t bx = __float_as_uint(bv.x), by = __float_as_uint(bv.y);
#pragma unroll
            for (int mt = 0; mt < 2; mt++)
                MMA_TF32(acc[mt][j], a[mt], bx, by);
        }
    }
}

// ---------------- pipelined tf32 GEMM, 128 rows/CTA, 512 threads ----------------
// out[MTOT x N] = epi(A[MTOT x K] @ W + bias). A concat at KSPLIT from A1.
// MODE: 0 none, 1 relu, 2 LayerNorm+relu. CVTK: A cols < CVTK need tf32 rounding.
// RND: store outputs pre-rounded to tf32.
#define OFF_R 768
#define OFF_A 1792
#define SA_F  (128 * 36)
#define OFF_B (OFF_A + 2 * SA_F)    // 11008

template<int K, int N, int KSPLIT, int MODE, int CVTK, bool RND>
__global__ void __launch_bounds__(512)
g2(const float* __restrict__ A0, int strideA0,
   const float* __restrict__ A1, int strideA1,
   const float* __restrict__ packB, const float* __restrict__ bias,
   const float* __restrict__ lng, const float* __restrict__ lnb,
   float* __restrict__ out)
{
    extern __shared__ float sm[];
    constexpr int NCH = K / 32, NT = N / 32, SB = 32 * N;
    const int tid = threadIdx.x;
    const int m0 = blockIdx.x * 128;
    const uint32_t sbase = smem_u32(sm);

    for (int i = tid; i < N; i += 512) sm[i] = bias[i];
    if (MODE == 2)
        for (int i = tid; i < N; i += 512) { sm[256 + i] = lng[i]; sm[512 + i] = lnb[i]; }

    const int lane = tid & 31, w = tid >> 5;
    const int wr = w >> 2, wc = w & 3;
    const int t = lane & 3, g = lane >> 2;
    const int r0 = wr * 32;

    float acc[2][NT][4];
#pragma unroll
    for (int mt = 0; mt < 2; mt++)
#pragma unroll
        for (int j = 0; j < NT; j++)
            acc[mt][j][0] = acc[mt][j][1] = acc[mt][j][2] = acc[mt][j][3] = 0.f;

    auto issue = [&](int c, int buf) {
        const int gc0 = c * 32;
#pragma unroll
        for (int e = tid; e < 1024; e += 512) {
            const int row = e >> 3, cq = e & 7;
            const int gcol = gc0 + cq * 4;
            const float* src;
            if (KSPLIT && gcol >= KSPLIT)
                src = A1 + (size_t)(m0 + row) * strideA1 + (gcol - KSPLIT);
            else
                src = A0 + (size_t)(m0 + row) * strideA0 + gcol;
            cp16(sbase + (uint32_t)(OFF_A + buf * SA_F + row * 36 + cq * 4) * 4, src);
        }
        const float* bs = packB + (size_t)c * SB;
        for (int e = tid; e < SB / 4; e += 512)
            cp16(sbase + (uint32_t)(OFF_B + buf * SB + e * 4) * 4, bs + e * 4);
    };
    issue(0, 0);
    CP_COMMIT();

#pragma unroll 1
    for (int c = 0; c < NCH; c++) {
        if (c + 1 < NCH) { issue(c + 1, (c + 1) & 1); CP_COMMIT(); CP_WAIT(1); }
        else             { CP_WAIT(0); }
        __syncthreads();
        const float*  sA  = sm + OFF_A + (c & 1) * SA_F;
        const float2* sBf = (const float2*)(sm + OFF_B + (c & 1) * SB);
        const bool docvt = (CVTK >= K) ? true : (CVTK == 0 ? false : (c * 32 < CVTK));
        if (docvt) chunk_mma<NT, true>(sA, sBf, acc, r0, wc, t, g);
        else       chunk_mma<NT, false>(sA, sBf, acc, r0, wc, t, g);
        __syncthreads();
    }

    if (MODE == 2) {
        // bias
#pragma unroll
        for (int mt = 0; mt < 2; mt++)
#pragma unroll
            for (int j = 0; j < NT; j++) {
                const int n0 = wc * (N / 4) + j * 8 + 2 * t;
                acc[mt][j][0] += sm[n0]; acc[mt][j][1] += sm[n0 + 1];
                acc[mt][j][2] += sm[n0]; acc[mt][j][3] += sm[n0 + 1];
            }
        // partial sums per (row, wc)
        float ps[2][2] = {{0,0},{0,0}}, pq[2][2] = {{0,0},{0,0}};
#pragma unroll
        for (int mt = 0; mt < 2; mt++)
#pragma unroll
            for (int j = 0; j < NT; j++) {
                ps[mt][0] += acc[mt][j][0] + acc[mt][j][1];
                pq[mt][0] += acc[mt][j][0] * acc[mt][j][0] + acc[mt][j][1] * acc[mt][j][1];
                ps[mt][1] += acc[mt][j][2] + acc[mt][j][3];
                pq[mt][1] += acc[mt][j][2] * acc[mt][j][2] + acc[mt][j][3] * acc[mt][j][3];
            }
#pragma unroll
        for (int mt = 0; mt < 2; mt++)
#pragma unroll
            for (int h = 0; h < 2; h++) {
                ps[mt][h] += __shfl_xor_sync(0xffffffffu, ps[mt][h], 1);
                ps[mt][h] += __shfl_xor_sync(0xffffffffu, ps[mt][h], 2);
                pq[mt][h] += __shfl_xor_sync(0xffffffffu, pq[mt][h], 1);
                pq[mt][h] += __shfl_xor_sync(0xffffffffu, pq[mt][h], 2);
            }
        if (t == 0) {
#pragma unroll
            for (int mt = 0; mt < 2; mt++)
#pragma unroll
                for (int h = 0; h < 2; h++) {
                    const int rl = r0 + mt * 16 + g + 8 * h;
                    sm[OFF_R + rl * 4 + wc]       = ps[mt][h];
                    sm[OFF_R + 512 + rl * 4 + wc] = pq[mt][h];
                }
        }
        __syncthreads();
        float mu[2][2], rs[2][2];
#pragma unroll
        for (int mt = 0; mt < 2; mt++)
#pragma unroll
            for (int h = 0; h < 2; h++) {
                const int rl = r0 + mt * 16 + g + 8 * h;
                const float s_ = sm[OFF_R + rl * 4] + sm[OFF_R + rl * 4 + 1]
                               + sm[OFF_R + rl * 4 + 2] + sm[OFF_R + rl * 4 + 3];
                const float q_ = sm[OFF_R + 512 + rl * 4] + sm[OFF_R + 512 + rl * 4 + 1]
                               + sm[OFF_R + 512 + rl * 4 + 2] + sm[OFF_R + 512 + rl * 4 + 3];
                const float m_ = s_ * (1.f / N);
                const float v_ = q_ * (1.f / N) - m_ * m_;
                mu[mt][h] = m_;
                rs[mt][h] = rsqrtf(v_ + 1e-5f);
            }
#pragma unroll
        for (int mt = 0; mt < 2; mt++)
#pragma unroll
            for (int j = 0; j < NT; j++) {
                const int n0 = wc * (N / 4) + j * 8 + 2 * t;
                const float g0 = sm[256 + n0], g1 = sm[256 + n0 + 1];
                const float b0 = sm[512 + n0], b1 = sm[512 + n0 + 1];
                float v0 = fmaxf((acc[mt][j][0] - mu[mt][0]) * rs[mt][0] * g0 + b0, 0.f);
                float v1 = fmaxf((acc[mt][j][1] - mu[mt][0]) * rs[mt][0] * g1 + b1, 0.f);
                float v2 = fmaxf((acc[mt][j][2] - mu[mt][1]) * rs[mt][1] * g0 + b0, 0.f);
                float v3 = fmaxf((acc[mt][j][3] - mu[mt][1]) * rs[mt][1] * g1 + b1, 0.f);
                if (RND) { v0 = f2tf_f(v0); v1 = f2tf_f(v1); v2 = f2tf_f(v2); v3 = f2tf_f(v3); }
                const size_t rA = (size_t)(m0 + r0 + mt * 16 + g);
                *(float2*)(out + rA * N + n0)       = make_float2(v0, v1);
                *(float2*)(out + (rA + 8) * N + n0) = make_float2(v2, v3);
            }
    } else {
#pragma unroll
        for (int mt = 0; mt < 2; mt++)
#pragma unroll
            for (int j = 0; j < NT; j++) {
                const int n0 = wc * (N / 4) + j * 8 + 2 * t;
                const float b0 = sm[n0], b1 = sm[n0 + 1];
                float v0 = acc[mt][j][0] + b0, v1 = acc[mt][j][1] + b1;
                float v2 = acc[mt][j][2] + b0, v3 = acc[mt][j][3] + b1;
                if (MODE == 1) {
                    v0 = fmaxf(v0, 0.f); v1 = fmaxf(v1, 0.f);
                    v2 = fmaxf(v2, 0.f); v3 = fmaxf(v3, 0.f);
                }
                if (RND) { v0 = f2tf_f(v0); v1 = f2tf_f(v1); v2 = f2tf_f(v2); v3 = f2tf_f(v3); }
                const size_t rA = (size_t)(m0 + r0 + mt * 16 + g);
                *(float2*)(out + rA * N + n0)       = make_float2(v0, v1);
                *(float2*)(out + (rA + 8) * N + n0) = make_float2(v2, v3);
            }
    }
}

// ---------------- attention (scalar fp32, validated; ctx stored tf32-rounded) ----------------
#define LD_QKV 196
#define LD_CTX 68
__global__ void __launch_bounds__(256)
attn_kernel(const float* __restrict__ qkv, float* __restrict__ ctxo)
{
    extern __shared__ float smA[];
    float* sQ = smA;
    float* sC = smA + 64 * LD_QKV;
    const int b = blockIdx.x, tid = threadIdx.x;
    const float* src = qkv + (size_t)b * 64 * 192;
    for (int i = tid; i < 64 * 192 / 4; i += 256) {
        int r = i / 48, c4 = i - r * 48;
        *(float4*)(sQ + r * LD_QKV + c4 * 4) = *(const float4*)(src + r * 192 + c4 * 4);
    }
    __syncthreads();
    {
        const int h = tid >> 6, q = tid & 63;
        float qv[16];
#pragma unroll
        for (int d = 0; d < 16; d++) qv[d] = sQ[q * LD_QKV + h * 16 + d];
        float m = -1e30f;
#pragma unroll 4
        for (int k = 0; k < 64; k++) {
            const float* kp = sQ + k * LD_QKV + 64 + h * 16;
            float s = 0.f;
#pragma unroll
            for (int d = 0; d < 16; d++) s = fmaf(qv[d], kp[d], s);
            m = fmaxf(m, s * 0.25f);
        }
        float ssum = 0.f, ctx[16];
#pragma unroll
        for (int d = 0; d < 16; d++) ctx[d] = 0.f;
#pragma unroll 2
        for (int k = 0; k < 64; k++) {
            const float* kp = sQ + k * LD_QKV + 64 + h * 16;
            float s = 0.f;
#pragma unroll
            for (int d = 0; d < 16; d++) s = fmaf(qv[d], kp[d], s);
            float p = __expf(fmaf(s, 0.25f, -m));
            ssum += p;
            const float* vp = sQ + k * LD_QKV + 128 + h * 16;
#pragma unroll
            for (int d = 0; d < 16; d++) ctx[d] = fmaf(p, vp[d], ctx[d]);
        }
        float inv = 1.f / ssum;
#pragma unroll
        for (int d = 0; d < 16; d++)
            sC[q * LD_CTX + h * 16 + d] = f2tf_f(ctx[d] * inv);
    }
    __syncthreads();
    float* go = ctxo + (size_t)b * 64 * 64;
    for (int i = tid; i < 64 * 64; i += 256) {
        int r = i >> 6, c = i & 63;
        go[i] = sC[r * LD_CTX + c];
    }
}

// ---------------- launch ----------------
extern "C" void kernel_launch(void* const* d_in, const int* in_sizes, int n_in,
                              void* d_out, int out_size)
{
    const float* obs    = (const float*)d_in[0];
    const float* enc_w1 = (const float*)d_in[1];
    const float* enc_b1 = (const float*)d_in[2];
    const float* enc_w2 = (const float*)d_in[3];
    const float* enc_b2 = (const float*)d_in[4];
    const float* inp_w  = (const float*)d_in[5];
    const float* inp_b  = (const float*)d_in[6];
    const float* out_w  = (const float*)d_in[7];
    const float* out_b  = (const float*)d_in[8];
    const float* int_w1 = (const float*)d_in[9];
    const float* int_b1 = (const float*)d_in[10];
    const float* ln_g   = (const float*)d_in[11];
    const float* ln_b   = (const float*)d_in[12];
    const float* int_w2 = (const float*)d_in[13];
    const float* int_b2 = (const float*)d_in[14];

    float* outE = (float*)d_out;
    const size_t esz = (size_t)MTOT * DOBS;
    float* outM = ((size_t)out_size > esz) ? outE + esz : nullptr;

    float *p_pack, *p_bc, *p_h, *p_qkv, *p_ctx, *p_z, *p_msgs;
    cudaGetSymbolAddress((void**)&p_pack, g_pack);
    cudaGetSymbolAddress((void**)&p_bc,   g_bc);
    cudaGetSymbolAddress((void**)&p_h,    g_h);
    cudaGetSymbolAddress((void**)&p_qkv,  g_qkv);
    cudaGetSymbolAddress((void**)&p_ctx,  g_ctx);
    cudaGetSymbolAddress((void**)&p_z,    g_z);
    cudaGetSymbolAddress((void**)&p_msgs, g_msgs_s);
    float* msgs = outM ? outM : p_msgs;

    auto smB = [](int N) { return (OFF_B + 2 * 32 * N) * 4; };
    const int sm_e1 = smB(128);
    const int sm_e2 = smB(64);
    const int sm_qk = smB(192);
    const int sm_i1 = smB(256);
    const int sm_i2 = smB(128);
    const int sm_at = (64 * LD_QKV + 64 * LD_CTX) * 4;

    cudaFuncSetAttribute((g2<128, 128, 0, 1, 128, true>),  cudaFuncAttributeMaxDynamicSharedMemorySize, sm_e1);
    cudaFuncSetAttribute((g2<128, 64, 0, 0, 0, false>),    cudaFuncAttributeMaxDynamicSharedMemorySize, sm_e2);
    cudaFuncSetAttribute((g2<64, 192, 0, 0, 64, false>),   cudaFuncAttributeMaxDynamicSharedMemorySize, sm_qk);
    cudaFuncSetAttribute((g2<192, 256, 128, 2, 128, true>), cudaFuncAttributeMaxDynamicSharedMemorySize, sm_i1);
    cudaFuncSetAttribute((g2<256, 128, 0, 0, 0, false>),   cudaFuncAttributeMaxDynamicSharedMemorySize, sm_i2);
    cudaFuncSetAttribute(attn_kernel, cudaFuncAttributeMaxDynamicSharedMemorySize, sm_at);

    // L1: all weight folding + packing in one launch
    pack_all<<<(59648 + 255) / 256, 256>>>(enc_w1, enc_w2, inp_w, out_w, out_b,
                                           int_w1, int_b1, int_w2);

    const int G = MTOT / 128;  // 2048 tiles

    // L2: enc1  h = relu(obs @ W1 + b1)            (h stored tf32-rounded)
    g2<128, 128, 0, 1, 128, true><<<G, 512, sm_e1>>>(obs, 128, nullptr, 0, p_pack + P_E1,
                                                     enc_b1, nullptr, nullptr, p_h);
    // L3: enc2  msgs = h @ W2 + b2                 (msgs full precision: output)
    g2<128, 64, 0, 0, 0, false><<<G, 512, sm_e2>>>(p_h, 128, nullptr, 0, p_pack + P_E2,
                                                   enc_b2, nullptr, nullptr, msgs);
    // L4: qkv = msgs @ in_proj + b                 (full precision for scalar attention)
    g2<64, 192, 0, 0, 64, false><<<G, 512, sm_qk>>>(msgs, 64, nullptr, 0, p_pack + P_QK,
                                                    inp_b, nullptr, nullptr, p_qkv);
    // L5: attention -> ctx (tf32-rounded)
    attn_kernel<<<NBATCH, 256, sm_at>>>(p_qkv, p_ctx);
    // L6: int1  z = LN(relu([obs|ctx] @ Wcomb + bc))  (z stored tf32-rounded)
    g2<192, 256, 128, 2, 128, true><<<G, 512, sm_i1>>>(obs, 128, p_ctx, 64, p_pack + P_I1,
                                                       p_bc, ln_g, ln_b, p_z);
    // L7: int2  enriched = z @ W2' + b2'
    g2<256, 128, 0, 0, 0, false><<<G, 512, sm_i2>>>(p_z, 256, nullptr, 0, p_pack + P_I2,
                                                    int_b2, nullptr, nullptr, outE);
}

// round 8
// speedup vs baseline: 1.2764x; 1.2026x over previous
#include <cuda_runtime.h>
#include <cuda_fp16.h>
#include <math.h>
#include <stdint.h>

// ---------------- problem constants ----------------
#define NBATCH 4096
#define NTOK   64
#define MTOT   (NBATCH * NTOK)
#define DOBS   128

// ---------------- packed fp16 weight fragments (uint2 per lane per k16xn8 tile) ----------------
#define PH_E1  0        // (128/16)*(128/8)*32 = 4096
#define PH_E2  4096     // 8*8*32   = 2048
#define PH_QK  6144     // 4*24*32  = 3072
#define PH_I2  9216     // 16*16*32 = 8192
#define PH_I1  17408    // 12*32*32 = 12288
#define PH_TOT 29696
__device__ uint2  g_packh[PH_TOT];
__device__ float  g_bc[256];
__device__ __half g_obs16[(size_t)MTOT * 128];
__device__ __half g_h16[(size_t)MTOT * 128];
__device__ __half g_msgs16[(size_t)MTOT * 64];
__device__ float  g_qkv[(size_t)MTOT * 192];
__device__ __half g_ctx16[(size_t)MTOT * 64];
__device__ __half g_z16[(size_t)MTOT * 256];
__device__ float  g_msgs_s[(size_t)MTOT * 64];

// ---------------- helpers ----------------
__device__ __forceinline__ uint32_t smem_u32(const void* p) {
    uint32_t a;
    asm("{ .reg .u64 t; cvta.to.shared.u64 t, %1; cvt.u32.u64 %0, t; }" : "=r"(a) : "l"(p));
    return a;
}
__device__ __forceinline__ void cp16(uint32_t dst, const void* src) {
    asm volatile("cp.async.ca.shared.global [%0], [%1], 16;" :: "r"(dst), "l"(src));
}
#define CP_COMMIT() asm volatile("cp.async.commit_group;" ::: "memory")
#define CP_WAIT(n)  asm volatile("cp.async.wait_group %0;" :: "n"(n) : "memory")

#define MMA_F16(acc, a, bx, by)                                                      \
    asm volatile("mma.sync.aligned.m16n8k16.row.col.f32.f16.f16.f32 "                \
                 "{%0,%1,%2,%3}, {%4,%5,%6,%7}, {%8,%9}, {%0,%1,%2,%3};"             \
                 : "+f"((acc)[0]), "+f"((acc)[1]), "+f"((acc)[2]), "+f"((acc)[3])    \
                 : "r"((a)[0]), "r"((a)[1]), "r"((a)[2]), "r"((a)[3]),               \
                   "r"(bx), "r"(by))

__device__ __forceinline__ uint32_t h2u(__half2 h) { return *reinterpret_cast<uint32_t*>(&h); }

// ---------------- fp32 -> fp16 tensor conversion ----------------
__global__ void conv16(const float* __restrict__ s, __half* __restrict__ d, int n4)
{
    int i = blockIdx.x * blockDim.x + threadIdx.x;
    if (i >= n4) return;
    float4 v = ((const float4*)s)[i];
    uint2 o;
    o.x = h2u(__floats2half2_rn(v.x, v.y));
    o.y = h2u(__floats2half2_rn(v.z, v.w));
    ((uint2*)d)[i] = o;
}

// ---------------- single prep kernel: fold + pack fp16 fragments ----------------
__device__ __forceinline__ float wcomb_elem(int k, int n,
                                            const float* __restrict__ out_w,
                                            const float* __restrict__ int_w1)
{
    if (k < 128) return int_w1[(size_t)k * 256 + n];
    const int c = k - 128;
    float s = 0.f;
#pragma unroll 4
    for (int m = 0; m < 64; m++)
        s = fmaf(out_w[c * 64 + m], int_w1[(size_t)(128 + m) * 256 + n], s);
    return s;
}

__global__ void pack_all(const float* __restrict__ enc_w1, const float* __restrict__ enc_w2,
                         const float* __restrict__ inp_w,  const float* __restrict__ out_w,
                         const float* __restrict__ out_b,  const float* __restrict__ int_w1,
                         const float* __restrict__ int_b1, const float* __restrict__ int_w2)
{
    const int gid = blockIdx.x * blockDim.x + threadIdx.x;
    int p, N = 0;
    const float* W = nullptr;
    uint2* dst = nullptr;
    bool i1 = false;
    if (gid < 4096)        { p = gid;         W = enc_w1; dst = g_packh + PH_E1; N = 128; }
    else if (gid < 6144)   { p = gid - 4096;  W = enc_w2; dst = g_packh + PH_E2; N = 64;  }
    else if (gid < 9216)   { p = gid - 6144;  W = inp_w;  dst = g_packh + PH_QK; N = 192; }
    else if (gid < 17408)  { p = gid - 9216;  W = int_w2; dst = g_packh + PH_I2; N = 128; }
    else if (gid < 29696)  { p = gid - 17408; dst = g_packh + PH_I1; N = 256; i1 = true; }
    else if (gid < 29952) {
        const int n = gid - 29696;
        float s = int_b1[n];
        for (int m = 0; m < 64; m++) s = fmaf(out_b[m], int_w1[(size_t)(128 + m) * 256 + n], s);
        g_bc[n] = s;
        return;
    } else return;

    const int lane = p & 31;
    const int tile = p >> 5;
    const int nt = N >> 3;
    const int j = tile % nt, kk = tile / nt;
    const int t = lane & 3, g = lane >> 2;
    const int k0 = kk * 16, n = j * 8 + g;
    float w0, w1, w2, w3;
    if (i1) {
        w0 = wcomb_elem(k0 + 2 * t,     n, out_w, int_w1);
        w1 = wcomb_elem(k0 + 2 * t + 1, n, out_w, int_w1);
        w2 = wcomb_elem(k0 + 2 * t + 8, n, out_w, int_w1);
        w3 = wcomb_elem(k0 + 2 * t + 9, n, out_w, int_w1);
    } else {
        w0 = W[(size_t)(k0 + 2 * t) * N + n];
        w1 = W[(size_t)(k0 + 2 * t + 1) * N + n];
        w2 = W[(size_t)(k0 + 2 * t + 8) * N + n];
        w3 = W[(size_t)(k0 + 2 * t + 9) * N + n];
    }
    uint2 v;
    v.x = h2u(__floats2half2_rn(w0, w1));
    v.y = h2u(__floats2half2_rn(w2, w3));
    dst[p] = v;
}

// ---------------- pipelined fp16 GEMM, 128 rows/CTA, 512 threads ----------------
// out[MTOT x N] = epi(A[MTOT x K] @ W + bias). A fp16 (concat at KSPLIT from A1).
// MODE: 0 none, 1 relu, 2 LayerNorm+relu.
// W16: 0 = fp32 out only; 1 = fp16 out16 only; 2 = both.
#define OFF_R 768
#define OFF_A 1792          // words; A chunk = 128 rows x 20 words (40 fp16, pad)
#define SA_W  2560
#define OFF_B 6912          // words; B chunk = N*16 words

template<int K, int N, int KSPLIT, int MODE, int W16>
__global__ void __launch_bounds__(512)
g3(const __half* __restrict__ A0, int sA0x, const __half* __restrict__ A1, int sA1x,
   const uint2* __restrict__ packB, const float* __restrict__ bias,
   const float* __restrict__ lng, const float* __restrict__ lnb,
   float* __restrict__ out, __half* __restrict__ out16)
{
    extern __shared__ float sm[];
    constexpr int NCH = K / 32, NT = N / 32, SB_W = N * 16;
    const int tid = threadIdx.x;
    const int m0 = blockIdx.x * 128;
    const uint32_t sbase = smem_u32(sm);

    for (int i = tid; i < N; i += 512) sm[i] = bias[i];
    if (MODE == 2)
        for (int i = tid; i < N; i += 512) { sm[256 + i] = lng[i]; sm[512 + i] = lnb[i]; }

    const int lane = tid & 31, w = tid >> 5;
    const int wr = w >> 2, wc = w & 3;
    const int t = lane & 3, g = lane >> 2;
    const int r0 = wr * 32;

    float acc[2][NT][4];
#pragma unroll
    for (int mt = 0; mt < 2; mt++)
#pragma unroll
        for (int j = 0; j < NT; j++)
            acc[mt][j][0] = acc[mt][j][1] = acc[mt][j][2] = acc[mt][j][3] = 0.f;

    auto issue = [&](int c, int buf) {
        const int gc0 = c * 32;
        {   // A: 128 rows x 32 fp16 cols = 512 x 16B ops (1/thread)
            const int row = tid >> 2, cq = tid & 3;
            const int gcol = gc0 + cq * 8;
            const __half* src;
            if (KSPLIT && gcol >= KSPLIT)
                src = A1 + (size_t)(m0 + row) * sA1x + (gcol - KSPLIT);
            else
                src = A0 + (size_t)(m0 + row) * sA0x + gcol;
            cp16(sbase + (uint32_t)(OFF_A + buf * SA_W + row * 20 + cq * 4) * 4, src);
        }
        const char* bs = (const char*)(packB + (size_t)c * 8 * N);
        for (int e = tid; e < N * 4; e += 512)
            cp16(sbase + (uint32_t)(OFF_B + buf * SB_W) * 4 + (uint32_t)e * 16, bs + e * 16);
    };
    issue(0, 0);
    CP_COMMIT();

#pragma unroll 1
    for (int c = 0; c < NCH; c++) {
        if (c + 1 < NCH) { issue(c + 1, (c + 1) & 1); CP_COMMIT(); CP_WAIT(1); }
        else             { CP_WAIT(0); }
        __syncthreads();
        const uint32_t* sw = (const uint32_t*)(sm + OFF_A + (c & 1) * SA_W);
        const uint2*    sB = (const uint2*)(sm + OFF_B + (c & 1) * SB_W);
#pragma unroll
        for (int kk2 = 0; kk2 < 2; kk2++) {
            uint32_t a[2][4];
#pragma unroll
            for (int mt = 0; mt < 2; mt++) {
                const int rb = r0 + mt * 16 + g;
                const int b0 = rb * 20 + kk2 * 8;
                const int b1 = (rb + 8) * 20 + kk2 * 8;
                a[mt][0] = sw[b0 + t];
                a[mt][1] = sw[b1 + t];
                a[mt][2] = sw[b0 + t + 4];
                a[mt][3] = sw[b1 + t + 4];
            }
#pragma unroll
            for (int j = 0; j < NT; j++) {
                const uint2 bv = sB[(size_t)(kk2 * (N / 8) + wc * NT + j) * 32 + lane];
#pragma unroll
                for (int mt = 0; mt < 2; mt++)
                    MMA_F16(acc[mt][j], a[mt], bv.x, bv.y);
            }
        }
        __syncthreads();
    }

    // ---------------- epilogue ----------------
    if (MODE == 2) {
#pragma unroll
        for (int mt = 0; mt < 2; mt++)
#pragma unroll
            for (int j = 0; j < NT; j++) {
                const int n0 = wc * (N / 4) + j * 8 + 2 * t;
                acc[mt][j][0] += sm[n0]; acc[mt][j][1] += sm[n0 + 1];
                acc[mt][j][2] += sm[n0]; acc[mt][j][3] += sm[n0 + 1];
            }
        float ps[2][2] = {{0,0},{0,0}}, pq[2][2] = {{0,0},{0,0}};
#pragma unroll
        for (int mt = 0; mt < 2; mt++)
#pragma unroll
            for (int j = 0; j < NT; j++) {
                ps[mt][0] += acc[mt][j][0] + acc[mt][j][1];
                pq[mt][0] += acc[mt][j][0] * acc[mt][j][0] + acc[mt][j][1] * acc[mt][j][1];
                ps[mt][1] += acc[mt][j][2] + acc[mt][j][3];
                pq[mt][1] += acc[mt][j][2] * acc[mt][j][2] + acc[mt][j][3] * acc[mt][j][3];
            }
#pragma unroll
        for (int mt = 0; mt < 2; mt++)
#pragma unroll
            for (int h = 0; h < 2; h++) {
                ps[mt][h] += __shfl_xor_sync(0xffffffffu, ps[mt][h], 1);
                ps[mt][h] += __shfl_xor_sync(0xffffffffu, ps[mt][h], 2);
                pq[mt][h] += __shfl_xor_sync(0xffffffffu, pq[mt][h], 1);
                pq[mt][h] += __shfl_xor_sync(0xffffffffu, pq[mt][h], 2);
            }
        if (t == 0) {
#pragma unroll
            for (int mt = 0; mt < 2; mt++)
#pragma unroll
                for (int h = 0; h < 2; h++) {
                    const int rl = r0 + mt * 16 + g + 8 * h;
                    sm[OFF_R + rl * 4 + wc]       = ps[mt][h];
                    sm[OFF_R + 512 + rl * 4 + wc] = pq[mt][h];
                }
        }
        __syncthreads();
        float mu[2][2], rs[2][2];
#pragma unroll
        for (int mt = 0; mt < 2; mt++)
#pragma unroll
            for (int h = 0; h < 2; h++) {
                const int rl = r0 + mt * 16 + g + 8 * h;
                const float s_ = sm[OFF_R + rl * 4] + sm[OFF_R + rl * 4 + 1]
                               + sm[OFF_R + rl * 4 + 2] + sm[OFF_R + rl * 4 + 3];
                const float q_ = sm[OFF_R + 512 + rl * 4] + sm[OFF_R + 512 + rl * 4 + 1]
                               + sm[OFF_R + 512 + rl * 4 + 2] + sm[OFF_R + 512 + rl * 4 + 3];
                const float m_ = s_ * (1.f / N);
                const float v_ = q_ * (1.f / N) - m_ * m_;
                mu[mt][h] = m_;
                rs[mt][h] = rsqrtf(v_ + 1e-5f);
            }
#pragma unroll
        for (int mt = 0; mt < 2; mt++)
#pragma unroll
            for (int j = 0; j < NT; j++) {
                const int n0 = wc * (N / 4) + j * 8 + 2 * t;
                const float g0 = sm[256 + n0], g1 = sm[256 + n0 + 1];
                const float b0 = sm[512 + n0], b1 = sm[512 + n0 + 1];
                const float v0 = fmaxf((acc[mt][j][0] - mu[mt][0]) * rs[mt][0] * g0 + b0, 0.f);
                const float v1 = fmaxf((acc[mt][j][1] - mu[mt][0]) * rs[mt][0] * g1 + b1, 0.f);
                const float v2 = fmaxf((acc[mt][j][2] - mu[mt][1]) * rs[mt][1] * g0 + b0, 0.f);
                const float v3 = fmaxf((acc[mt][j][3] - mu[mt][1]) * rs[mt][1] * g1 + b1, 0.f);
                const size_t rA = (size_t)(m0 + r0 + mt * 16 + g);
                if (W16 >= 1) {
                    *(__half2*)(out16 + rA * N + n0)       = __floats2half2_rn(v0, v1);
                    *(__half2*)(out16 + (rA + 8) * N + n0) = __floats2half2_rn(v2, v3);
                }
                if (W16 != 1) {
                    *(float2*)(out + rA * N + n0)       = make_float2(v0, v1);
                    *(float2*)(out + (rA + 8) * N + n0) = make_float2(v2, v3);
                }
            }
    } else {
#pragma unroll
        for (int mt = 0; mt < 2; mt++)
#pragma unroll
            for (int j = 0; j < NT; j++) {
                const int n0 = wc * (N / 4) + j * 8 + 2 * t;
                const float b0 = sm[n0], b1 = sm[n0 + 1];
                float v0 = acc[mt][j][0] + b0, v1 = acc[mt][j][1] + b1;
                float v2 = acc[mt][j][2] + b0, v3 = acc[mt][j][3] + b1;
                if (MODE == 1) {
                    v0 = fmaxf(v0, 0.f); v1 = fmaxf(v1, 0.f);
                    v2 = fmaxf(v2, 0.f); v3 = fmaxf(v3, 0.f);
                }
                const size_t rA = (size_t)(m0 + r0 + mt * 16 + g);
                if (W16 >= 1) {
                    *(__half2*)(out16 + rA * N + n0)       = __floats2half2_rn(v0, v1);
                    *(__half2*)(out16 + (rA + 8) * N + n0) = __floats2half2_rn(v2, v3);
                }
                if (W16 != 1) {
                    *(float2*)(out + rA * N + n0)       = make_float2(v0, v1);
                    *(float2*)(out + (rA + 8) * N + n0) = make_float2(v2, v3);
                }
            }
    }
}

// ---------------- attention (scalar fp32, validated; ctx -> fp16) ----------------
#define LD_QKV 196
#define LD_CTX 68
__global__ void __launch_bounds__(256)
attn_kernel(const float* __restrict__ qkv, __half* __restrict__ ctxo)
{
    extern __shared__ float smA[];
    float* sQ = smA;
    float* sC = smA + 64 * LD_QKV;
    const int b = blockIdx.x, tid = threadIdx.x;
    const float* src = qkv + (size_t)b * 64 * 192;
    for (int i = tid; i < 64 * 192 / 4; i += 256) {
        int r = i / 48, c4 = i - r * 48;
        *(float4*)(sQ + r * LD_QKV + c4 * 4) = *(const float4*)(src + r * 192 + c4 * 4);
    }
    __syncthreads();
    {
        const int h = tid >> 6, q = tid & 63;
        float qv[16];
#pragma unroll
        for (int d = 0; d < 16; d++) qv[d] = sQ[q * LD_QKV + h * 16 + d];
        float m = -1e30f;
#pragma unroll 4
        for (int k = 0; k < 64; k++) {
            const float* kp = sQ + k * LD_QKV + 64 + h * 16;
            float s = 0.f;
#pragma unroll
            for (int d = 0; d < 16; d++) s = fmaf(qv[d], kp[d], s);
            m = fmaxf(m, s * 0.25f);
        }
        float ssum = 0.f, ctx[16];
#pragma unroll
        for (int d = 0; d < 16; d++) ctx[d] = 0.f;
#pragma unroll 2
        for (int k = 0; k < 64; k++) {
            const float* kp = sQ + k * LD_QKV + 64 + h * 16;
            float s = 0.f;
#pragma unroll
            for (int d = 0; d < 16; d++) s = fmaf(qv[d], kp[d], s);
            float p = __expf(fmaf(s, 0.25f, -m));
            ssum += p;
            const float* vp = sQ + k * LD_QKV + 128 + h * 16;
#pragma unroll
            for (int d = 0; d < 16; d++) ctx[d] = fmaf(p, vp[d], ctx[d]);
        }
        float inv = 1.f / ssum;
#pragma unroll
        for (int d = 0; d < 16; d++) sC[q * LD_CTX + h * 16 + d] = ctx[d] * inv;
    }
    __syncthreads();
    __half* go = ctxo + (size_t)b * 64 * 64;
    for (int i = tid; i < 64 * 64; i += 256) {
        int r = i >> 6, c = i & 63;
        go[i] = __float2half_rn(sC[r * LD_CTX + c]);
    }
}

// ---------------- launch ----------------
extern "C" void kernel_launch(void* const* d_in, const int* in_sizes, int n_in,
                              void* d_out, int out_size)
{
    const float* obs    = (const float*)d_in[0];
    const float* enc_w1 = (const float*)d_in[1];
    const float* enc_b1 = (const float*)d_in[2];
    const float* enc_w2 = (const float*)d_in[3];
    const float* enc_b2 = (const float*)d_in[4];
    const float* inp_w  = (const float*)d_in[5];
    const float* inp_b  = (const float*)d_in[6];
    const float* out_w  = (const float*)d_in[7];
    const float* out_b  = (const float*)d_in[8];
    const float* int_w1 = (const float*)d_in[9];
    const float* int_b1 = (const float*)d_in[10];
    const float* ln_g   = (const float*)d_in[11];
    const float* ln_b   = (const float*)d_in[12];
    const float* int_w2 = (const float*)d_in[13];
    const float* int_b2 = (const float*)d_in[14];

    float* outE = (float*)d_out;
    const size_t esz = (size_t)MTOT * DOBS;
    float* outM = ((size_t)out_size > esz) ? outE + esz : nullptr;

    uint2* p_pack;
    float *p_bc, *p_qkv, *p_msgs;
    __half *p_obs16, *p_h16, *p_msgs16, *p_ctx16, *p_z16;
    cudaGetSymbolAddress((void**)&p_pack,  g_packh);
    cudaGetSymbolAddress((void**)&p_bc,    g_bc);
    cudaGetSymbolAddress((void**)&p_obs16, g_obs16);
    cudaGetSymbolAddress((void**)&p_h16,   g_h16);
    cudaGetSymbolAddress((void**)&p_msgs16, g_msgs16);
    cudaGetSymbolAddress((void**)&p_qkv,   g_qkv);
    cudaGetSymbolAddress((void**)&p_ctx16, g_ctx16);
    cudaGetSymbolAddress((void**)&p_z16,   g_z16);
    cudaGetSymbolAddress((void**)&p_msgs,  g_msgs_s);
    float* msgs = outM ? outM : p_msgs;

    auto smB = [](int N) { return (OFF_B + 2 * N * 16) * 4; };
    const int sm_e1 = smB(128);
    const int sm_e2 = smB(64);
    const int sm_qk = smB(192);
    const int sm_i1 = smB(256);
    const int sm_i2 = smB(128);
    const int sm_at = (64 * LD_QKV + 64 * LD_CTX) * 4;

    cudaFuncSetAttribute((g3<128, 128, 0, 1, 1>),   cudaFuncAttributeMaxDynamicSharedMemorySize, sm_e1);
    cudaFuncSetAttribute((g3<128, 64, 0, 0, 2>),    cudaFuncAttributeMaxDynamicSharedMemorySize, sm_e2);
    cudaFuncSetAttribute((g3<64, 192, 0, 0, 0>),    cudaFuncAttributeMaxDynamicSharedMemorySize, sm_qk);
    cudaFuncSetAttribute((g3<192, 256, 128, 2, 1>), cudaFuncAttributeMaxDynamicSharedMemorySize, sm_i1);
    cudaFuncSetAttribute((g3<256, 128, 0, 0, 0>),   cudaFuncAttributeMaxDynamicSharedMemorySize, sm_i2);
    cudaFuncSetAttribute(attn_kernel, cudaFuncAttributeMaxDynamicSharedMemorySize, sm_at);

    // prep: pack weights (fp16 fragments) + convert obs to fp16
    pack_all<<<(29952 + 255) / 256, 256>>>(enc_w1, enc_w2, inp_w, out_w, out_b,
                                           int_w1, int_b1, int_w2);
    conv16<<<(MTOT * 128 / 4 + 511) / 512, 512>>>(obs, p_obs16, MTOT * 128 / 4);

    const int G = MTOT / 128;  // 2048 tiles

    // enc1: h16 = relu(obs @ W1 + b1)
    g3<128, 128, 0, 1, 1><<<G, 512, sm_e1>>>(p_obs16, 128, nullptr, 0, p_pack + PH_E1,
                                             enc_b1, nullptr, nullptr, nullptr, p_h16);
    // enc2: msgs = h @ W2 + b2  (fp32 output + fp16 for qkv)
    g3<128, 64, 0, 0, 2><<<G, 512, sm_e2>>>(p_h16, 128, nullptr, 0, p_pack + PH_E2,
                                            enc_b2, nullptr, nullptr, msgs, p_msgs16);
    // qkv = msgs @ in_proj + b  (fp32 for scalar attention)
    g3<64, 192, 0, 0, 0><<<G, 512, sm_qk>>>(p_msgs16, 64, nullptr, 0, p_pack + PH_QK,
                                            inp_b, nullptr, nullptr, p_qkv, nullptr);
    // attention -> ctx16
    attn_kernel<<<NBATCH, 256, sm_at>>>(p_qkv, p_ctx16);
    // int1 (out-proj folded): z16 = LN+relu([obs|ctx] @ Wcomb + bc)
    g3<192, 256, 128, 2, 1><<<G, 512, sm_i1>>>(p_obs16, 128, p_ctx16, 64, p_pack + PH_I1,
                                               p_bc, ln_g, ln_b, nullptr, p_z16);
    // int2: enriched = z @ W2' + b2'
    g3<256, 128, 0, 0, 0><<<G, 512, sm_i2>>>(p_z16, 256, nullptr, 0, p_pack + PH_I2,
                                             int_b2, nullptr, nullptr, outE, nullptr);
}